// round 1
// baseline (speedup 1.0000x reference)
#include <cuda_runtime.h>

// Problem constants
#define HID   1024
#define MTOT  4096          // BSZ * SEQ = 4 * 1024
#define NHEAD 16
#define HD    64
#define BH    64            // BSZ * NHEAD

// Scratch (device globals — no allocation allowed)
__device__ float g_q[4u * 1024u * 1024u];
__device__ float g_k[4u * 1024u * 1024u];
__device__ float g_v[4u * 1024u * 1024u];
__device__ float g_a[4u * 1024u * 1024u];

// ---------------------------------------------------------------------------
// SGEMM (NT): C[M x N] = A[M x K] * W[N x K]^T  (both row-major, K contiguous)
// Block tile 128x128, BK=8, 256 threads, 8x8 micro-tile.
// Column mapping col = tx + 16*j -> conflict-free Bs reads, coalesced C stores.
// ---------------------------------------------------------------------------
__device__ __forceinline__ void gemm_body(const float* __restrict__ A,
                                          const float* __restrict__ W,
                                          float* __restrict__ C)
{
    __shared__ float As[8][128];
    __shared__ float Bs[8][128];

    const int tid  = threadIdx.x;
    const int tx   = tid & 15;
    const int ty   = tid >> 4;
    const int row0 = blockIdx.y * 128;
    const int col0 = blockIdx.x * 128;

    // cooperative load indices: each thread loads one float4 of A and W per k-tile
    const int lr = tid >> 1;          // 0..127
    const int lk = (tid & 1) * 4;     // 0 or 4
    const float* Ap = A + (size_t)(row0 + lr) * HID + lk;
    const float* Wp = W + (size_t)(col0 + lr) * HID + lk;

    float acc[8][8];
#pragma unroll
    for (int i = 0; i < 8; ++i)
#pragma unroll
        for (int j = 0; j < 8; ++j) acc[i][j] = 0.0f;

    for (int k0 = 0; k0 < HID; k0 += 8) {
        float4 av = *(const float4*)(Ap + k0);
        float4 wv = *(const float4*)(Wp + k0);
        As[lk + 0][lr] = av.x; As[lk + 1][lr] = av.y;
        As[lk + 2][lr] = av.z; As[lk + 3][lr] = av.w;
        Bs[lk + 0][lr] = wv.x; Bs[lk + 1][lr] = wv.y;
        Bs[lk + 2][lr] = wv.z; Bs[lk + 3][lr] = wv.w;
        __syncthreads();

#pragma unroll
        for (int kk = 0; kk < 8; ++kk) {
            float a[8], b[8];
            float4 a0 = *(const float4*)&As[kk][ty * 8];
            float4 a1 = *(const float4*)&As[kk][ty * 8 + 4];
            a[0] = a0.x; a[1] = a0.y; a[2] = a0.z; a[3] = a0.w;
            a[4] = a1.x; a[5] = a1.y; a[6] = a1.z; a[7] = a1.w;
#pragma unroll
            for (int j = 0; j < 8; ++j) b[j] = Bs[kk][tx + 16 * j];
#pragma unroll
            for (int i = 0; i < 8; ++i)
#pragma unroll
                for (int j = 0; j < 8; ++j)
                    acc[i][j] = fmaf(a[i], b[j], acc[i][j]);
        }
        __syncthreads();
    }

#pragma unroll
    for (int i = 0; i < 8; ++i) {
        float* Cp = C + (size_t)(row0 + ty * 8 + i) * HID + col0 + tx;
#pragma unroll
        for (int j = 0; j < 8; ++j) Cp[16 * j] = acc[i][j];
    }
}

__global__ void __launch_bounds__(256)
qkv_gemm_kernel(const float* __restrict__ x,
                const float* __restrict__ wq,
                const float* __restrict__ wk,
                const float* __restrict__ wv)
{
    const float* W = (blockIdx.z == 0) ? wq : (blockIdx.z == 1) ? wk : wv;
    float*       C = (blockIdx.z == 0) ? g_q : (blockIdx.z == 1) ? g_k : g_v;
    gemm_body(x, W, C);
}

__global__ void __launch_bounds__(256)
proj_gemm_kernel(const float* __restrict__ wo, float* __restrict__ out)
{
    gemm_body(g_a, wo, out);
}

// ---------------------------------------------------------------------------
// Flash attention over contiguous per-(b,h) 1024x64 blocks.
// Br = Bc = 64, 256 threads (16x16), 4x4 micro-tiles.
// Row r = 4*ty + i, col c = 16*j + tx  (strided cols -> conflict-free smem).
// Online softmax; row reductions via shfl_xor across the 16 tx lanes.
// ---------------------------------------------------------------------------
__global__ void __launch_bounds__(256) flash_kernel()
{
    extern __shared__ float sm[];
    float* sQ = sm;                 // [64][65]  (scaled Q)
    float* sK = sQ + 64 * 65;       // [64][65]
    float* sV = sK + 64 * 65;       // [64][64]
    float* sP = sV + 64 * 64;       // [64][65]

    const int bh = blockIdx.y;      // b*16 + h
    const int qt = blockIdx.x;      // q tile 0..15
    const float* Qb = g_q + bh * 65536 + qt * 4096;
    const float* Kb = g_k + bh * 65536;
    const float* Vb = g_v + bh * 65536;
    float*       Ob = g_a + bh * 65536 + qt * 4096;

    const int tid = threadIdx.x;
    const int tx  = tid & 15;
    const int ty  = tid >> 4;

    // load Q tile, folding in softmax scale 1/sqrt(64) = 0.125
    for (int idx = tid; idx < 4096; idx += 256) {
        int r = idx >> 6, c = idx & 63;
        sQ[r * 65 + c] = Qb[idx] * 0.125f;
    }

    float m_prev[4], l_run[4], o[4][4];
#pragma unroll
    for (int i = 0; i < 4; ++i) {
        m_prev[i] = -1e30f;
        l_run[i]  = 0.0f;
#pragma unroll
        for (int j = 0; j < 4; ++j) o[i][j] = 0.0f;
    }

    for (int kt = 0; kt < 16; ++kt) {
        __syncthreads();   // previous PV / Q-load done before overwriting K,V
        const float* Kp = Kb + kt * 4096;
        const float* Vp = Vb + kt * 4096;
        for (int idx = tid; idx < 4096; idx += 256) {
            int r = idx >> 6, c = idx & 63;
            sK[r * 65 + c] = Kp[idx];
            sV[idx]        = Vp[idx];
        }
        __syncthreads();

        // S = Qs * Ks^T  (4x4 per thread)
        float s[4][4];
#pragma unroll
        for (int i = 0; i < 4; ++i)
#pragma unroll
            for (int j = 0; j < 4; ++j) s[i][j] = 0.0f;

#pragma unroll 8
        for (int d = 0; d < 64; ++d) {
            float q0 = sQ[(ty * 4 + 0) * 65 + d];
            float q1 = sQ[(ty * 4 + 1) * 65 + d];
            float q2 = sQ[(ty * 4 + 2) * 65 + d];
            float q3 = sQ[(ty * 4 + 3) * 65 + d];
            float k0 = sK[(tx)      * 65 + d];
            float k1 = sK[(16 + tx) * 65 + d];
            float k2 = sK[(32 + tx) * 65 + d];
            float k3 = sK[(48 + tx) * 65 + d];
            s[0][0] = fmaf(q0, k0, s[0][0]); s[0][1] = fmaf(q0, k1, s[0][1]);
            s[0][2] = fmaf(q0, k2, s[0][2]); s[0][3] = fmaf(q0, k3, s[0][3]);
            s[1][0] = fmaf(q1, k0, s[1][0]); s[1][1] = fmaf(q1, k1, s[1][1]);
            s[1][2] = fmaf(q1, k2, s[1][2]); s[1][3] = fmaf(q1, k3, s[1][3]);
            s[2][0] = fmaf(q2, k0, s[2][0]); s[2][1] = fmaf(q2, k1, s[2][1]);
            s[2][2] = fmaf(q2, k2, s[2][2]); s[2][3] = fmaf(q2, k3, s[2][3]);
            s[3][0] = fmaf(q3, k0, s[3][0]); s[3][1] = fmaf(q3, k1, s[3][1]);
            s[3][2] = fmaf(q3, k2, s[3][2]); s[3][3] = fmaf(q3, k3, s[3][3]);
        }

        // online softmax update (per-row stats replicated across tx lanes)
#pragma unroll
        for (int i = 0; i < 4; ++i) {
            float tm = fmaxf(fmaxf(s[i][0], s[i][1]), fmaxf(s[i][2], s[i][3]));
#pragma unroll
            for (int off = 1; off < 16; off <<= 1)
                tm = fmaxf(tm, __shfl_xor_sync(0xffffffffu, tm, off));
            float mn    = fmaxf(m_prev[i], tm);
            float alpha = __expf(m_prev[i] - mn);
            m_prev[i]   = mn;
            float rs = 0.0f;
#pragma unroll
            for (int j = 0; j < 4; ++j) {
                float p = __expf(s[i][j] - mn);
                sP[(ty * 4 + i) * 65 + 16 * j + tx] = p;
                rs += p;
            }
#pragma unroll
            for (int off = 1; off < 16; off <<= 1)
                rs += __shfl_xor_sync(0xffffffffu, rs, off);
            l_run[i] = l_run[i] * alpha + rs;
#pragma unroll
            for (int j = 0; j < 4; ++j) o[i][j] *= alpha;
        }
        __syncthreads();   // sP visible to all

        // O += P * V
#pragma unroll 8
        for (int t = 0; t < 64; ++t) {
            float p0 = sP[(ty * 4 + 0) * 65 + t];
            float p1 = sP[(ty * 4 + 1) * 65 + t];
            float p2 = sP[(ty * 4 + 2) * 65 + t];
            float p3 = sP[(ty * 4 + 3) * 65 + t];
            float v0 = sV[t * 64 + tx];
            float v1 = sV[t * 64 + 16 + tx];
            float v2 = sV[t * 64 + 32 + tx];
            float v3 = sV[t * 64 + 48 + tx];
            o[0][0] = fmaf(p0, v0, o[0][0]); o[0][1] = fmaf(p0, v1, o[0][1]);
            o[0][2] = fmaf(p0, v2, o[0][2]); o[0][3] = fmaf(p0, v3, o[0][3]);
            o[1][0] = fmaf(p1, v0, o[1][0]); o[1][1] = fmaf(p1, v1, o[1][1]);
            o[1][2] = fmaf(p1, v2, o[1][2]); o[1][3] = fmaf(p1, v3, o[1][3]);
            o[2][0] = fmaf(p2, v0, o[2][0]); o[2][1] = fmaf(p2, v1, o[2][1]);
            o[2][2] = fmaf(p2, v2, o[2][2]); o[2][3] = fmaf(p2, v3, o[2][3]);
            o[3][0] = fmaf(p3, v0, o[3][0]); o[3][1] = fmaf(p3, v1, o[3][1]);
            o[3][2] = fmaf(p3, v2, o[3][2]); o[3][3] = fmaf(p3, v3, o[3][3]);
        }
    }

#pragma unroll
    for (int i = 0; i < 4; ++i) {
        float inv = 1.0f / l_run[i];
#pragma unroll
        for (int j = 0; j < 4; ++j)
            Ob[(ty * 4 + i) * 64 + 16 * j + tx] = o[i][j] * inv;
    }
}

// ---------------------------------------------------------------------------
extern "C" void kernel_launch(void* const* d_in, const int* in_sizes, int n_in,
                              void* d_out, int out_size)
{
    const float* x  = (const float*)d_in[0];
    const float* wq = (const float*)d_in[1];
    const float* wk = (const float*)d_in[2];
    const float* wv = (const float*)d_in[3];
    const float* wo = (const float*)d_in[4];
    float* out = (float*)d_out;

    const int smem_bytes = (64 * 65 * 3 + 64 * 64) * (int)sizeof(float); // 66304
    cudaFuncSetAttribute(flash_kernel,
                         cudaFuncAttributeMaxDynamicSharedMemorySize, smem_bytes);

    // 1) fused QKV projections: 3 x (4096x1024 @ 1024x1024^T)
    qkv_gemm_kernel<<<dim3(8, 32, 3), 256>>>(x, wq, wk, wv);
    // 2) flash attention over 64 (b,h) blocks x 16 q-tiles
    flash_kernel<<<dim3(16, BH), 256, smem_bytes>>>();
    // 3) output projection: 4096x1024 @ 1024x1024^T
    proj_gemm_kernel<<<dim3(8, 32), 256>>>(wo, out);
}

// round 3
// speedup vs baseline: 1.5873x; 1.5873x over previous
#include <cuda_runtime.h>
#include <cuda_bf16.h>
#include <cstdint>

#define HID   1024
#define BH    64

// ------------------------- device scratch (no alloc allowed) ---------------
__device__ float g_q[4194304];
__device__ float g_k[4194304];
__device__ float g_v[4194304];
__device__ float g_a[4194304];

__device__ __nv_bfloat16 g_xh[4194304], g_xl[4194304];
__device__ __nv_bfloat16 g_wh[3145728], g_wl[3145728];   // wq|wk|wv
__device__ __nv_bfloat16 g_woh[1048576], g_wol[1048576];
__device__ __nv_bfloat16 g_ah[4194304], g_al[4194304];

// ------------------------- helpers -----------------------------------------
__device__ __forceinline__ uint32_t smem_u32(const void* p) {
    uint32_t a;
    asm("{ .reg .u64 t; cvta.to.shared.u64 t, %1; cvt.u32.u64 %0, t; }"
        : "=r"(a) : "l"(p));
    return a;
}

#define SWZ128(bo) ((bo) ^ (((bo) >> 3) & 0x70))

#define LDSM4(r, addr) \
    asm volatile("ldmatrix.sync.aligned.m8n8.x4.shared.b16 {%0,%1,%2,%3}, [%4];" \
                 : "=r"((r)[0]), "=r"((r)[1]), "=r"((r)[2]), "=r"((r)[3])       \
                 : "r"(addr))

#define MMA16816(d, a, b0, b1) \
    asm volatile("mma.sync.aligned.m16n8k16.row.col.f32.bf16.bf16.f32 "         \
                 "{%0,%1,%2,%3}, {%4,%5,%6,%7}, {%8,%9}, {%0,%1,%2,%3};"        \
                 : "+f"((d)[0]), "+f"((d)[1]), "+f"((d)[2]), "+f"((d)[3])       \
                 : "r"((a)[0]), "r"((a)[1]), "r"((a)[2]), "r"((a)[3]),          \
                   "r"(b0), "r"(b1))

// ------------------------- fp32 -> bf16 hi/lo split ------------------------
__device__ __forceinline__ void split4_store(float4 v, __nv_bfloat16* hi,
                                             __nv_bfloat16* lo, int i) {
    __nv_bfloat16 h0 = __float2bfloat16(v.x), h1 = __float2bfloat16(v.y);
    __nv_bfloat16 h2 = __float2bfloat16(v.z), h3 = __float2bfloat16(v.w);
    __nv_bfloat16 l0 = __float2bfloat16(v.x - __bfloat162float(h0));
    __nv_bfloat16 l1 = __float2bfloat16(v.y - __bfloat162float(h1));
    __nv_bfloat16 l2 = __float2bfloat16(v.z - __bfloat162float(h2));
    __nv_bfloat16 l3 = __float2bfloat16(v.w - __bfloat162float(h3));
    __nv_bfloat162* H = (__nv_bfloat162*)hi;
    __nv_bfloat162* L = (__nv_bfloat162*)lo;
    __nv_bfloat162 p;
    p.x = h0; p.y = h1; H[2*i]   = p;
    p.x = h2; p.y = h3; H[2*i+1] = p;
    p.x = l0; p.y = l1; L[2*i]   = p;
    p.x = l2; p.y = l3; L[2*i+1] = p;
}

__global__ void __launch_bounds__(256) split_x_kernel(const float4* __restrict__ x) {
    int i = blockIdx.x * 256 + threadIdx.x;
    split4_store(x[i], g_xh, g_xl, i);
}
__global__ void __launch_bounds__(256) split_w_kernel(const float4* __restrict__ wq,
                                                      const float4* __restrict__ wk,
                                                      const float4* __restrict__ wv,
                                                      const float4* __restrict__ wo) {
    int z = blockIdx.z;
    const float4* s = (z == 0) ? wq : (z == 1) ? wk : (z == 2) ? wv : wo;
    __nv_bfloat16* hi = (z < 3) ? g_wh + (size_t)z * 1048576 : g_woh;
    __nv_bfloat16* lo = (z < 3) ? g_wl + (size_t)z * 1048576 : g_wol;
    int i = blockIdx.x * 256 + threadIdx.x;
    split4_store(s[i], hi, lo, i);
}
__global__ void __launch_bounds__(256) split_a_kernel() {
    int i = blockIdx.x * 256 + threadIdx.x;
    split4_store(((const float4*)g_a)[i], g_ah, g_al, i);
}

// ------------------------- HMMA GEMM body ----------------------------------
// C[4096 x 1024] = A * B^T via mma.sync m16n8k16 bf16, 3-term split.
// Block 128x128, BK=64, 512 threads = 4x4 warps, warp tile 32x32.
__device__ __forceinline__ void mma_gemm_body(const __nv_bfloat16* __restrict__ Ah,
                                              const __nv_bfloat16* __restrict__ Al,
                                              const __nv_bfloat16* __restrict__ Bh,
                                              const __nv_bfloat16* __restrict__ Bl,
                                              float* __restrict__ C) {
    extern __shared__ char smem[];
    const uint32_t sb = smem_u32(smem);
    const uint32_t SA_H = 0, SA_L = 16384, SB_H = 32768, SB_L = 49152;

    const int tid  = threadIdx.x;
    const int lane = tid & 31, wid = tid >> 5;
    const int wm = wid >> 2, wn = wid & 3;
    const int n0 = blockIdx.x * 128, m0 = blockIdx.y * 128;

    // ldmatrix address components (swizzle xor = (row&7)<<4 since rowpitch=128B)
    const int ra = wm * 32 + (lane & 15);           // A row, mi adds +16
    const uint32_t colA = (uint32_t)((lane >> 4) << 4);
    const uint32_t aX   = (uint32_t)((ra & 7) << 4);
    const uint32_t aB0  = sb + SA_H + (uint32_t)ra * 128;
    const uint32_t aB1  = aB0 + 16 * 128;

    const int q = lane >> 3, r = lane & 7;
    const int rb = wn * 32 + ((q >> 1) << 3) + r;   // B row, nj2 adds +16
    const uint32_t colB = (uint32_t)((q & 1) << 4);
    const uint32_t bX   = (uint32_t)((rb & 7) << 4);
    const uint32_t bB0  = sb + SB_H + (uint32_t)rb * 128;
    const uint32_t bB1  = bB0 + 16 * 128;

    float acc[2][4][4];
#pragma unroll
    for (int mi = 0; mi < 2; ++mi)
#pragma unroll
        for (int nj = 0; nj < 4; ++nj)
#pragma unroll
            for (int e = 0; e < 4; ++e) acc[mi][nj][e] = 0.0f;

    for (int k0 = 0; k0 < HID; k0 += 64) {
        if (k0) __syncthreads();
        // cooperative load: 4 tiles of 128x64 bf16 (16KB each), SW128-swizzled
        for (int t = tid; t < 1024; t += 512) {
            int row = t >> 3, c = t & 7;
            uint32_t so = SWZ128((uint32_t)(row * 128 + c * 16));
            const char* pa = (const char*)(Ah + (size_t)(m0 + row) * HID + k0) + c * 16;
            const char* pA = (const char*)(Al + (size_t)(m0 + row) * HID + k0) + c * 16;
            const char* pb = (const char*)(Bh + (size_t)(n0 + row) * HID + k0) + c * 16;
            const char* pB = (const char*)(Bl + (size_t)(n0 + row) * HID + k0) + c * 16;
            *(uint4*)(smem + SA_H + so) = *(const uint4*)pa;
            *(uint4*)(smem + SA_L + so) = *(const uint4*)pA;
            *(uint4*)(smem + SB_H + so) = *(const uint4*)pb;
            *(uint4*)(smem + SB_L + so) = *(const uint4*)pB;
        }
        __syncthreads();

#pragma unroll
        for (int ks = 0; ks < 4; ++ks) {
            const uint32_t cb = (uint32_t)(ks * 32);          // k16 step -> 32B
            const uint32_t offA = (cb + colA) ^ aX;
            const uint32_t offB = (cb + colB) ^ bX;

            uint32_t ah[2][4], al[2][4], bh[2][4], bl[2][4];
            LDSM4(ah[0], aB0 + offA);
            LDSM4(ah[1], aB1 + offA);
            LDSM4(al[0], aB0 + 16384 + offA);
            LDSM4(al[1], aB1 + 16384 + offA);
            LDSM4(bh[0], bB0 + offB);
            LDSM4(bh[1], bB1 + offB);
            LDSM4(bl[0], bB0 + 16384 + offB);
            LDSM4(bl[1], bB1 + 16384 + offB);

#pragma unroll
            for (int mi = 0; mi < 2; ++mi)
#pragma unroll
                for (int nj = 0; nj < 4; ++nj) {
                    const int g = nj >> 1, h = (nj & 1) * 2;
                    MMA16816(acc[mi][nj], ah[mi], bh[g][h], bh[g][h + 1]);
                    MMA16816(acc[mi][nj], ah[mi], bl[g][h], bl[g][h + 1]);
                    MMA16816(acc[mi][nj], al[mi], bh[g][h], bh[g][h + 1]);
                }
        }
    }

    // epilogue: fragment -> gmem (float2 per row-half)
    const int crow = m0 + wm * 32 + (lane >> 2);
    const int ccol = n0 + wn * 32 + (lane & 3) * 2;
#pragma unroll
    for (int mi = 0; mi < 2; ++mi)
#pragma unroll
        for (int nj = 0; nj < 4; ++nj) {
            float* p0 = C + (size_t)(crow + mi * 16) * HID + ccol + nj * 8;
            float* p1 = p0 + 8 * HID;
            *(float2*)p0 = make_float2(acc[mi][nj][0], acc[mi][nj][1]);
            *(float2*)p1 = make_float2(acc[mi][nj][2], acc[mi][nj][3]);
        }
}

__global__ void __launch_bounds__(512, 1) qkv_mma_kernel() {
    int z = blockIdx.z;
    const __nv_bfloat16* Bh = g_wh + (size_t)z * 1048576;
    const __nv_bfloat16* Bl = g_wl + (size_t)z * 1048576;
    float* C = (z == 0) ? g_q : (z == 1) ? g_k : g_v;
    mma_gemm_body(g_xh, g_xl, Bh, Bl, C);
}
__global__ void __launch_bounds__(512, 1) proj_mma_kernel(float* __restrict__ out) {
    mma_gemm_body(g_ah, g_al, g_woh, g_wol, out);
}

// ---------------------------------------------------------------------------
// Flash attention (fp32, unchanged)
// ---------------------------------------------------------------------------
__global__ void __launch_bounds__(256) flash_kernel()
{
    extern __shared__ float sm[];
    float* sQ = sm;
    float* sK = sQ + 64 * 65;
    float* sV = sK + 64 * 65;
    float* sP = sV + 64 * 64;

    const int bh = blockIdx.y;
    const int qt = blockIdx.x;
    const float* Qb = g_q + bh * 65536 + qt * 4096;
    const float* Kb = g_k + bh * 65536;
    const float* Vb = g_v + bh * 65536;
    float*       Ob = g_a + bh * 65536 + qt * 4096;

    const int tid = threadIdx.x;
    const int tx  = tid & 15;
    const int ty  = tid >> 4;

    for (int idx = tid; idx < 4096; idx += 256) {
        int rr = idx >> 6, c = idx & 63;
        sQ[rr * 65 + c] = Qb[idx] * 0.125f;
    }

    float m_prev[4], l_run[4], o[4][4];
#pragma unroll
    for (int i = 0; i < 4; ++i) {
        m_prev[i] = -1e30f;
        l_run[i]  = 0.0f;
#pragma unroll
        for (int j = 0; j < 4; ++j) o[i][j] = 0.0f;
    }

    for (int kt = 0; kt < 16; ++kt) {
        __syncthreads();
        const float* Kp = Kb + kt * 4096;
        const float* Vp = Vb + kt * 4096;
        for (int idx = tid; idx < 4096; idx += 256) {
            int rr = idx >> 6, c = idx & 63;
            sK[rr * 65 + c] = Kp[idx];
            sV[idx]         = Vp[idx];
        }
        __syncthreads();

        float s[4][4];
#pragma unroll
        for (int i = 0; i < 4; ++i)
#pragma unroll
            for (int j = 0; j < 4; ++j) s[i][j] = 0.0f;

#pragma unroll 8
        for (int d = 0; d < 64; ++d) {
            float q0 = sQ[(ty * 4 + 0) * 65 + d];
            float q1 = sQ[(ty * 4 + 1) * 65 + d];
            float q2 = sQ[(ty * 4 + 2) * 65 + d];
            float q3 = sQ[(ty * 4 + 3) * 65 + d];
            float k0 = sK[(tx)      * 65 + d];
            float k1 = sK[(16 + tx) * 65 + d];
            float k2 = sK[(32 + tx) * 65 + d];
            float k3 = sK[(48 + tx) * 65 + d];
            s[0][0] = fmaf(q0, k0, s[0][0]); s[0][1] = fmaf(q0, k1, s[0][1]);
            s[0][2] = fmaf(q0, k2, s[0][2]); s[0][3] = fmaf(q0, k3, s[0][3]);
            s[1][0] = fmaf(q1, k0, s[1][0]); s[1][1] = fmaf(q1, k1, s[1][1]);
            s[1][2] = fmaf(q1, k2, s[1][2]); s[1][3] = fmaf(q1, k3, s[1][3]);
            s[2][0] = fmaf(q2, k0, s[2][0]); s[2][1] = fmaf(q2, k1, s[2][1]);
            s[2][2] = fmaf(q2, k2, s[2][2]); s[2][3] = fmaf(q2, k3, s[2][3]);
            s[3][0] = fmaf(q3, k0, s[3][0]); s[3][1] = fmaf(q3, k1, s[3][1]);
            s[3][2] = fmaf(q3, k2, s[3][2]); s[3][3] = fmaf(q3, k3, s[3][3]);
        }

#pragma unroll
        for (int i = 0; i < 4; ++i) {
            float tm = fmaxf(fmaxf(s[i][0], s[i][1]), fmaxf(s[i][2], s[i][3]));
#pragma unroll
            for (int off = 1; off < 16; off <<= 1)
                tm = fmaxf(tm, __shfl_xor_sync(0xffffffffu, tm, off));
            float mn    = fmaxf(m_prev[i], tm);
            float alpha = __expf(m_prev[i] - mn);
            m_prev[i]   = mn;
            float rs = 0.0f;
#pragma unroll
            for (int j = 0; j < 4; ++j) {
                float p = __expf(s[i][j] - mn);
                sP[(ty * 4 + i) * 65 + 16 * j + tx] = p;
                rs += p;
            }
#pragma unroll
            for (int off = 1; off < 16; off <<= 1)
                rs += __shfl_xor_sync(0xffffffffu, rs, off);
            l_run[i] = l_run[i] * alpha + rs;
#pragma unroll
            for (int j = 0; j < 4; ++j) o[i][j] *= alpha;
        }
        __syncthreads();

#pragma unroll 8
        for (int t = 0; t < 64; ++t) {
            float p0 = sP[(ty * 4 + 0) * 65 + t];
            float p1 = sP[(ty * 4 + 1) * 65 + t];
            float p2 = sP[(ty * 4 + 2) * 65 + t];
            float p3 = sP[(ty * 4 + 3) * 65 + t];
            float v0 = sV[t * 64 + tx];
            float v1 = sV[t * 64 + 16 + tx];
            float v2 = sV[t * 64 + 32 + tx];
            float v3 = sV[t * 64 + 48 + tx];
            o[0][0] = fmaf(p0, v0, o[0][0]); o[0][1] = fmaf(p0, v1, o[0][1]);
            o[0][2] = fmaf(p0, v2, o[0][2]); o[0][3] = fmaf(p0, v3, o[0][3]);
            o[1][0] = fmaf(p1, v0, o[1][0]); o[1][1] = fmaf(p1, v1, o[1][1]);
            o[1][2] = fmaf(p1, v2, o[1][2]); o[1][3] = fmaf(p1, v3, o[1][3]);
            o[2][0] = fmaf(p2, v0, o[2][0]); o[2][1] = fmaf(p2, v1, o[2][1]);
            o[2][2] = fmaf(p2, v2, o[2][2]); o[2][3] = fmaf(p2, v3, o[2][3]);
            o[3][0] = fmaf(p3, v0, o[3][0]); o[3][1] = fmaf(p3, v1, o[3][1]);
            o[3][2] = fmaf(p3, v2, o[3][2]); o[3][3] = fmaf(p3, v3, o[3][3]);
        }
    }

#pragma unroll
    for (int i = 0; i < 4; ++i) {
        float inv = 1.0f / l_run[i];
#pragma unroll
        for (int j = 0; j < 4; ++j)
            Ob[(ty * 4 + i) * 64 + 16 * j + tx] = o[i][j] * inv;
    }
}

// ---------------------------------------------------------------------------
extern "C" void kernel_launch(void* const* d_in, const int* in_sizes, int n_in,
                              void* d_out, int out_size)
{
    const float* x  = (const float*)d_in[0];
    const float* wq = (const float*)d_in[1];
    const float* wk = (const float*)d_in[2];
    const float* wv = (const float*)d_in[3];
    const float* wo = (const float*)d_in[4];
    float* out = (float*)d_out;

    const int flash_smem = (64 * 65 * 3 + 64 * 64) * (int)sizeof(float); // 66304
    const int gemm_smem  = 65536;
    cudaFuncSetAttribute(flash_kernel,
                         cudaFuncAttributeMaxDynamicSharedMemorySize, flash_smem);
    cudaFuncSetAttribute(qkv_mma_kernel,
                         cudaFuncAttributeMaxDynamicSharedMemorySize, gemm_smem);
    cudaFuncSetAttribute(proj_mma_kernel,
                         cudaFuncAttributeMaxDynamicSharedMemorySize, gemm_smem);

    split_x_kernel<<<4096, 256>>>((const float4*)x);
    split_w_kernel<<<dim3(1024, 1, 4), 256>>>((const float4*)wq, (const float4*)wk,
                                              (const float4*)wv, (const float4*)wo);
    qkv_mma_kernel<<<dim3(8, 32, 3), 512, gemm_smem>>>();
    flash_kernel<<<dim3(16, BH), 256, flash_smem>>>();
    split_a_kernel<<<4096, 256>>>();
    proj_mma_kernel<<<dim3(8, 32), 512, gemm_smem>>>(out);
}

// round 6
// speedup vs baseline: 2.6108x; 1.6448x over previous
#include <cuda_runtime.h>
#include <cuda_bf16.h>
#include <cstdint>

#define HID   1024

// ------------------------- device scratch (no alloc allowed) ---------------
__device__ __nv_bfloat16 g_xh[4194304], g_xl[4194304];
__device__ __nv_bfloat16 g_wh[3145728], g_wl[3145728];   // wq|wk|wv
__device__ __nv_bfloat16 g_woh[1048576], g_wol[1048576];
__device__ __nv_bfloat16 g_qh[4194304], g_ql[4194304];   // flat (b,s,o), Q pre-scaled
__device__ __nv_bfloat16 g_kh[4194304], g_kl[4194304];
__device__ __nv_bfloat16 g_vh[4194304], g_vl[4194304];
__device__ __nv_bfloat16 g_ah[4194304], g_al[4194304];   // attention out, flat (b,s,o)

// ------------------------- helpers -----------------------------------------
__device__ __forceinline__ uint32_t smem_u32(const void* p) {
    uint32_t a;
    asm("{ .reg .u64 t; cvta.to.shared.u64 t, %1; cvt.u32.u64 %0, t; }"
        : "=r"(a) : "l"(p));
    return a;
}

#define SWZ128(bo) ((bo) ^ (((bo) >> 3) & 0x70))

#define LDSM4(r, addr) \
    asm volatile("ldmatrix.sync.aligned.m8n8.x4.shared.b16 {%0,%1,%2,%3}, [%4];" \
                 : "=r"((r)[0]), "=r"((r)[1]), "=r"((r)[2]), "=r"((r)[3])       \
                 : "r"(addr))

#define LDSM4T(r, addr) \
    asm volatile("ldmatrix.sync.aligned.m8n8.x4.trans.shared.b16 {%0,%1,%2,%3}, [%4];" \
                 : "=r"((r)[0]), "=r"((r)[1]), "=r"((r)[2]), "=r"((r)[3])       \
                 : "r"(addr))

#define MMA16816(d, a, b0, b1) \
    asm volatile("mma.sync.aligned.m16n8k16.row.col.f32.bf16.bf16.f32 "         \
                 "{%0,%1,%2,%3}, {%4,%5,%6,%7}, {%8,%9}, {%0,%1,%2,%3};"        \
                 : "+f"((d)[0]), "+f"((d)[1]), "+f"((d)[2]), "+f"((d)[3])       \
                 : "r"((a)[0]), "r"((a)[1]), "r"((a)[2]), "r"((a)[3]),          \
                   "r"(b0), "r"(b1))

#define CP_ASYNC16(dst, src) \
    asm volatile("cp.async.cg.shared.global [%0], [%1], 16;" \
                 :: "r"(dst), "l"(src) : "memory")
#define CP_COMMIT()  asm volatile("cp.async.commit_group;" ::: "memory")
#define CP_WAIT0()   asm volatile("cp.async.wait_group 0;" ::: "memory")

// pack two floats into bf16x2 reg: low half = first arg, high half = second
__device__ __forceinline__ uint32_t packbf(float lo, float hi) {
    uint32_t r;
    asm("cvt.rn.bf16x2.f32 %0, %1, %2;" : "=r"(r) : "f"(hi), "f"(lo));
    return r;
}

__device__ __forceinline__ void split_store2(float x, float y,
                                             __nv_bfloat16* H, __nv_bfloat16* L,
                                             size_t idx) {
    __nv_bfloat16 hx = __float2bfloat16(x), hy = __float2bfloat16(y);
    __nv_bfloat162 h2, l2;
    h2.x = hx; h2.y = hy;
    l2.x = __float2bfloat16(x - __bfloat162float(hx));
    l2.y = __float2bfloat16(y - __bfloat162float(hy));
    *(__nv_bfloat162*)(H + idx) = h2;
    *(__nv_bfloat162*)(L + idx) = l2;
}

// ------------------------- fp32 -> bf16 hi/lo split ------------------------
__device__ __forceinline__ void split4_store(float4 v, __nv_bfloat16* hi,
                                             __nv_bfloat16* lo, int i) {
    __nv_bfloat16 h0 = __float2bfloat16(v.x), h1 = __float2bfloat16(v.y);
    __nv_bfloat16 h2 = __float2bfloat16(v.z), h3 = __float2bfloat16(v.w);
    __nv_bfloat162* H = (__nv_bfloat162*)hi;
    __nv_bfloat162* L = (__nv_bfloat162*)lo;
    __nv_bfloat162 p;
    p.x = h0; p.y = h1; H[2*i]   = p;
    p.x = h2; p.y = h3; H[2*i+1] = p;
    p.x = __float2bfloat16(v.x - __bfloat162float(h0));
    p.y = __float2bfloat16(v.y - __bfloat162float(h1));
    L[2*i]   = p;
    p.x = __float2bfloat16(v.z - __bfloat162float(h2));
    p.y = __float2bfloat16(v.w - __bfloat162float(h3));
    L[2*i+1] = p;
}

__global__ void __launch_bounds__(256) split_x_kernel(const float4* __restrict__ x) {
    int i = blockIdx.x * 256 + threadIdx.x;
    split4_store(x[i], g_xh, g_xl, i);
}
__global__ void __launch_bounds__(256) split_w_kernel(const float4* __restrict__ wq,
                                                      const float4* __restrict__ wk,
                                                      const float4* __restrict__ wv,
                                                      const float4* __restrict__ wo) {
    int z = blockIdx.z;
    const float4* s = (z == 0) ? wq : (z == 1) ? wk : (z == 2) ? wv : wo;
    __nv_bfloat16* hi = (z < 3) ? g_wh + (size_t)z * 1048576 : g_woh;
    __nv_bfloat16* lo = (z < 3) ? g_wl + (size_t)z * 1048576 : g_wol;
    int i = blockIdx.x * 256 + threadIdx.x;
    split4_store(s[i], hi, lo, i);
}

// ------------------------- HMMA GEMM body ----------------------------------
// C[4096 x 1024] = A * B^T via mma.sync m16n8k16 bf16, 3-term split.
// Block 128x128, BK=64, 512 threads, warp tile 32x32.
// SPLIT_OUT=true: write bf16 hi/lo in the SAME flat (b,s,o) layout (raw view!)
template <bool SPLIT_OUT>
__device__ __forceinline__ void mma_gemm_body(const __nv_bfloat16* __restrict__ Ah,
                                              const __nv_bfloat16* __restrict__ Al,
                                              const __nv_bfloat16* __restrict__ Bh,
                                              const __nv_bfloat16* __restrict__ Bl,
                                              float* __restrict__ C,
                                              __nv_bfloat16* __restrict__ Oh,
                                              __nv_bfloat16* __restrict__ Ol,
                                              float scale) {
    extern __shared__ char smem[];
    const uint32_t sb = smem_u32(smem);
    const uint32_t SA_H = 0, SA_L = 16384, SB_H = 32768, SB_L = 49152;

    const int tid  = threadIdx.x;
    const int lane = tid & 31, wid = tid >> 5;
    const int wm = wid >> 2, wn = wid & 3;
    const int n0 = blockIdx.x * 128, m0 = blockIdx.y * 128;

    const int ra = wm * 32 + (lane & 15);
    const uint32_t colA = (uint32_t)((lane >> 4) << 4);
    const uint32_t aX   = (uint32_t)((ra & 7) << 4);
    const uint32_t aB0  = sb + SA_H + (uint32_t)ra * 128;
    const uint32_t aB1  = aB0 + 16 * 128;

    const int q = lane >> 3, r = lane & 7;
    const int rb = wn * 32 + ((q >> 1) << 3) + r;
    const uint32_t colB = (uint32_t)((q & 1) << 4);
    const uint32_t bX   = (uint32_t)((rb & 7) << 4);
    const uint32_t bB0  = sb + SB_H + (uint32_t)rb * 128;
    const uint32_t bB1  = bB0 + 16 * 128;

    float acc[2][4][4];
#pragma unroll
    for (int mi = 0; mi < 2; ++mi)
#pragma unroll
        for (int nj = 0; nj < 4; ++nj)
#pragma unroll
            for (int e = 0; e < 4; ++e) acc[mi][nj][e] = 0.0f;

    for (int k0 = 0; k0 < HID; k0 += 64) {
        if (k0) __syncthreads();
        for (int t = tid; t < 1024; t += 512) {
            int row = t >> 3, c = t & 7;
            uint32_t so = SWZ128((uint32_t)(row * 128 + c * 16));
            const char* pa = (const char*)(Ah + (size_t)(m0 + row) * HID + k0) + c * 16;
            const char* pA = (const char*)(Al + (size_t)(m0 + row) * HID + k0) + c * 16;
            const char* pb = (const char*)(Bh + (size_t)(n0 + row) * HID + k0) + c * 16;
            const char* pB = (const char*)(Bl + (size_t)(n0 + row) * HID + k0) + c * 16;
            *(uint4*)(smem + SA_H + so) = *(const uint4*)pa;
            *(uint4*)(smem + SA_L + so) = *(const uint4*)pA;
            *(uint4*)(smem + SB_H + so) = *(const uint4*)pb;
            *(uint4*)(smem + SB_L + so) = *(const uint4*)pB;
        }
        __syncthreads();

#pragma unroll
        for (int ks = 0; ks < 4; ++ks) {
            const uint32_t cb = (uint32_t)(ks * 32);
            const uint32_t offA = (cb + colA) ^ aX;
            const uint32_t offB = (cb + colB) ^ bX;

            uint32_t ah[2][4], al[2][4], bh[2][4], bl[2][4];
            LDSM4(ah[0], aB0 + offA);
            LDSM4(ah[1], aB1 + offA);
            LDSM4(al[0], aB0 + 16384 + offA);
            LDSM4(al[1], aB1 + 16384 + offA);
            LDSM4(bh[0], bB0 + offB);
            LDSM4(bh[1], bB1 + offB);
            LDSM4(bl[0], bB0 + 16384 + offB);
            LDSM4(bl[1], bB1 + 16384 + offB);

#pragma unroll
            for (int mi = 0; mi < 2; ++mi)
#pragma unroll
                for (int nj = 0; nj < 4; ++nj) {
                    const int g = nj >> 1, h = (nj & 1) * 2;
                    MMA16816(acc[mi][nj], ah[mi], bh[g][h], bh[g][h + 1]);
                    MMA16816(acc[mi][nj], ah[mi], bl[g][h], bl[g][h + 1]);
                    MMA16816(acc[mi][nj], al[mi], bh[g][h], bh[g][h + 1]);
                }
        }
    }

    const int crow = m0 + wm * 32 + (lane >> 2);
    const int ccol = n0 + wn * 32 + (lane & 3) * 2;
#pragma unroll
    for (int mi = 0; mi < 2; ++mi)
#pragma unroll
        for (int nj = 0; nj < 4; ++nj) {
            if (SPLIT_OUT) {
                // identity flat layout: raw view == flat storage
                size_t i0 = (size_t)(crow + mi * 16) * 1024 + (ccol + nj * 8);
                size_t i1 = i0 + 8 * 1024;
                split_store2(acc[mi][nj][0] * scale, acc[mi][nj][1] * scale, Oh, Ol, i0);
                split_store2(acc[mi][nj][2] * scale, acc[mi][nj][3] * scale, Oh, Ol, i1);
            } else {
                float* p0 = C + (size_t)(crow + mi * 16) * HID + ccol + nj * 8;
                float* p1 = p0 + 8 * HID;
                *(float2*)p0 = make_float2(acc[mi][nj][0], acc[mi][nj][1]);
                *(float2*)p1 = make_float2(acc[mi][nj][2], acc[mi][nj][3]);
            }
        }
}

__global__ void __launch_bounds__(512, 1) qkv_mma_kernel() {
    int z = blockIdx.z;
    const __nv_bfloat16* Bh = g_wh + (size_t)z * 1048576;
    const __nv_bfloat16* Bl = g_wl + (size_t)z * 1048576;
    __nv_bfloat16* Oh = (z == 0) ? g_qh : (z == 1) ? g_kh : g_vh;
    __nv_bfloat16* Ol = (z == 0) ? g_ql : (z == 1) ? g_kl : g_vl;
    float scale = (z == 0) ? 0.125f : 1.0f;   // fold softmax scale into Q
    mma_gemm_body<true>(g_xh, g_xl, Bh, Bl, nullptr, Oh, Ol, scale);
}
__global__ void __launch_bounds__(512, 1) proj_mma_kernel(float* __restrict__ out) {
    mma_gemm_body<false>(g_ah, g_al, g_woh, g_wol, out, nullptr, nullptr, 1.0f);
}

// ---------------------------------------------------------------------------
// Flash attention via HMMA, 3-term bf16 split on both QK^T and PV.
// Per-(b,h) head block = contiguous 65536-elt slice of the flat arrays (raw view).
// Block: 128 threads = 4 warps, Br=64 (16 rows/warp), Bc=64, 16 K-tiles.
// smem: 2 stages x {Kh,Kl,Vh,Vl} x 8KB = 64KB, cp.async double-buffered.
// ---------------------------------------------------------------------------
__device__ __forceinline__ void kv_issue(int tid, uint32_t sb, int stage,
                                         int kt, size_t base) {
    const size_t row0 = base + (size_t)kt * 64 * 64;
#pragma unroll
    for (int i = 0; i < 16; ++i) {
        int t = tid + i * 128;
        int tile = t >> 9;                 // 0:Kh 1:Kl 2:Vh 3:Vl
        int ww = t & 511, row = ww >> 3, c = ww & 7;
        const __nv_bfloat16* src =
            (tile == 0) ? g_kh : (tile == 1) ? g_kl : (tile == 2) ? g_vh : g_vl;
        src += row0 + (size_t)row * 64 + c * 8;
        uint32_t dst = sb + (uint32_t)stage * 32768 + (uint32_t)tile * 8192
                     + SWZ128((uint32_t)(row * 128 + c * 16));
        CP_ASYNC16(dst, src);
    }
}

__global__ void __launch_bounds__(128) flash_mma_kernel() {
    extern __shared__ char smem[];
    const uint32_t sb = smem_u32(smem);
    const int bh = blockIdx.y, qt = blockIdx.x;
    const int tid = threadIdx.x, lane = tid & 31, w = tid >> 5;
    const size_t base = (size_t)bh * 65536;

    // ---- stage Q (scaled, split) into stage0 area, load fragments ----
    {
        const __nv_bfloat16* Qhp = g_qh + base + (size_t)qt * 4096;
        const __nv_bfloat16* Qlp = g_ql + base + (size_t)qt * 4096;
#pragma unroll
        for (int i = 0; i < 8; ++i) {
            int t = tid + i * 128;
            int half = t >> 9, ww = t & 511, row = ww >> 3, c = ww & 7;
            const __nv_bfloat16* src = (half ? Qlp : Qhp) + row * 64 + c * 8;
            *(uint4*)(smem + half * 8192 + SWZ128((uint32_t)(row * 128 + c * 16)))
                = *(const uint4*)src;
        }
    }
    __syncthreads();

    uint32_t qh[4][4], ql[4][4];
    {
        const int ra = w * 16 + (lane & 15);
        const uint32_t colA = (uint32_t)((lane >> 4) << 4);
        const uint32_t aX   = (uint32_t)((ra & 7) << 4);
        const uint32_t qb   = sb + (uint32_t)ra * 128;
#pragma unroll
        for (int ks = 0; ks < 4; ++ks) {
            uint32_t off = ((uint32_t)(ks * 32) + colA) ^ aX;
            LDSM4(qh[ks], qb + off);
            LDSM4(ql[ks], qb + 8192 + off);
        }
    }
    __syncthreads();

    // K (B-operand, non-trans) addressing
    const int qq = lane >> 3, rr = lane & 7;
    const int rowK16 = ((qq >> 1) << 3) + rr;
    const uint32_t colBk = (uint32_t)((qq & 1) << 4);
    const uint32_t xK = (uint32_t)((rowK16 & 7) << 4);
    // V (B-operand via trans) addressing
    const int rowV = (lane & 7) + ((lane >> 3) & 1) * 8;
    const uint32_t colV16 = (uint32_t)(((lane >> 4) & 1) << 4);
    const uint32_t xV = (uint32_t)((rowV & 7) << 4);

    float o_[8][4];
#pragma unroll
    for (int t = 0; t < 8; ++t)
#pragma unroll
        for (int e = 0; e < 4; ++e) o_[t][e] = 0.0f;
    float m0v = -1e30f, m1v = -1e30f, l0 = 0.0f, l1 = 0.0f;

    kv_issue(tid, sb, 0, 0, base);
    CP_COMMIT();

    for (int kt = 0; kt < 16; ++kt) {
        CP_WAIT0();
        __syncthreads();
        if (kt + 1 < 16) {
            kv_issue(tid, sb, (kt + 1) & 1, kt + 1, base);
            CP_COMMIT();
        }
        const uint32_t kst = sb + (uint32_t)(kt & 1) * 32768;

        // ---- S = Qs K^T (3-term split) ----
        float s_[8][4];
#pragma unroll
        for (int t = 0; t < 8; ++t)
#pragma unroll
            for (int e = 0; e < 4; ++e) s_[t][e] = 0.0f;

#pragma unroll
        for (int sg = 0; sg < 4; ++sg) {
            const uint32_t rbase = kst + (uint32_t)((sg * 16 + rowK16) * 128);
#pragma unroll
            for (int ks = 0; ks < 4; ++ks) {
                const uint32_t off = ((uint32_t)(ks * 32) + colBk) ^ xK;
                uint32_t tkh[4], tkl[4];
                LDSM4(tkh, rbase + off);
                LDSM4(tkl, rbase + 8192 + off);
                MMA16816(s_[2*sg],   qh[ks], tkh[0], tkh[1]);
                MMA16816(s_[2*sg],   qh[ks], tkl[0], tkl[1]);
                MMA16816(s_[2*sg],   ql[ks], tkh[0], tkh[1]);
                MMA16816(s_[2*sg+1], qh[ks], tkh[2], tkh[3]);
                MMA16816(s_[2*sg+1], qh[ks], tkl[2], tkl[3]);
                MMA16816(s_[2*sg+1], ql[ks], tkh[2], tkh[3]);
            }
        }

        // ---- online softmax on fragments ----
        float mx0 = -1e30f, mx1 = -1e30f;
#pragma unroll
        for (int t = 0; t < 8; ++t) {
            mx0 = fmaxf(mx0, fmaxf(s_[t][0], s_[t][1]));
            mx1 = fmaxf(mx1, fmaxf(s_[t][2], s_[t][3]));
        }
        mx0 = fmaxf(mx0, __shfl_xor_sync(0xffffffffu, mx0, 1));
        mx0 = fmaxf(mx0, __shfl_xor_sync(0xffffffffu, mx0, 2));
        mx1 = fmaxf(mx1, __shfl_xor_sync(0xffffffffu, mx1, 1));
        mx1 = fmaxf(mx1, __shfl_xor_sync(0xffffffffu, mx1, 2));
        float mn0 = fmaxf(m0v, mx0), mn1 = fmaxf(m1v, mx1);
        float al0 = __expf(m0v - mn0), al1 = __expf(m1v - mn1);
        m0v = mn0; m1v = mn1;

        float rs0 = 0.0f, rs1 = 0.0f;
#pragma unroll
        for (int t = 0; t < 8; ++t) {
            s_[t][0] = __expf(s_[t][0] - mn0); rs0 += s_[t][0];
            s_[t][1] = __expf(s_[t][1] - mn0); rs0 += s_[t][1];
            s_[t][2] = __expf(s_[t][2] - mn1); rs1 += s_[t][2];
            s_[t][3] = __expf(s_[t][3] - mn1); rs1 += s_[t][3];
        }
        rs0 += __shfl_xor_sync(0xffffffffu, rs0, 1);
        rs0 += __shfl_xor_sync(0xffffffffu, rs0, 2);
        rs1 += __shfl_xor_sync(0xffffffffu, rs1, 1);
        rs1 += __shfl_xor_sync(0xffffffffu, rs1, 2);
        l0 = l0 * al0 + rs0;
        l1 = l1 * al1 + rs1;
#pragma unroll
        for (int t = 0; t < 8; ++t) {
            o_[t][0] *= al0; o_[t][1] *= al0;
            o_[t][2] *= al1; o_[t][3] *= al1;
        }

        // ---- O += P V (3-term split), P repacked in registers ----
        const uint32_t vst = kst + 16384;
#pragma unroll
        for (int j = 0; j < 4; ++j) {
            uint32_t pah[4], pal[4];
            {
                float c0 = s_[2*j][0],   c1 = s_[2*j][1];
                float c2 = s_[2*j][2],   c3 = s_[2*j][3];
                float d0 = s_[2*j+1][0], d1 = s_[2*j+1][1];
                float d2 = s_[2*j+1][2], d3 = s_[2*j+1][3];
                pah[0] = packbf(c0, c1);
                pah[1] = packbf(c2, c3);
                pah[2] = packbf(d0, d1);
                pah[3] = packbf(d2, d3);
                float r0f = c0 - __bfloat162float(__float2bfloat16(c0));
                float r1f = c1 - __bfloat162float(__float2bfloat16(c1));
                float r2f = c2 - __bfloat162float(__float2bfloat16(c2));
                float r3f = c3 - __bfloat162float(__float2bfloat16(c3));
                pal[0] = packbf(r0f, r1f);
                pal[1] = packbf(r2f, r3f);
                r0f = d0 - __bfloat162float(__float2bfloat16(d0));
                r1f = d1 - __bfloat162float(__float2bfloat16(d1));
                r2f = d2 - __bfloat162float(__float2bfloat16(d2));
                r3f = d3 - __bfloat162float(__float2bfloat16(d3));
                pal[2] = packbf(r0f, r1f);
                pal[3] = packbf(r2f, r3f);
            }
            const uint32_t rvb = vst + (uint32_t)((j * 16 + rowV) * 128);
#pragma unroll
            for (int dg = 0; dg < 4; ++dg) {
                const uint32_t off = ((uint32_t)(dg * 32) + colV16) ^ xV;
                uint32_t tvh[4], tvl[4];
                LDSM4T(tvh, rvb + off);
                LDSM4T(tvl, rvb + 8192 + off);
                MMA16816(o_[2*dg],   pah, tvh[0], tvh[1]);
                MMA16816(o_[2*dg],   pah, tvl[0], tvl[1]);
                MMA16816(o_[2*dg],   pal, tvh[0], tvh[1]);
                MMA16816(o_[2*dg+1], pah, tvh[2], tvh[3]);
                MMA16816(o_[2*dg+1], pah, tvl[2], tvl[3]);
                MMA16816(o_[2*dg+1], pal, tvh[2], tvh[3]);
            }
        }
    }

    // ---- epilogue: O/l -> bf16 hi/lo, identity flat layout (raw view) ----
    const float i0 = 1.0f / l0, i1 = 1.0f / l1;
    const int r0 = lane >> 2, cc = (lane & 3) * 2;
    const size_t idx0 = base + (size_t)(qt * 64 + w * 16 + r0) * 64 + cc;
    const size_t idx1 = idx0 + 8 * 64;
#pragma unroll
    for (int t = 0; t < 8; ++t) {
        split_store2(o_[t][0] * i0, o_[t][1] * i0, g_ah, g_al, idx0 + t * 8);
        split_store2(o_[t][2] * i1, o_[t][3] * i1, g_ah, g_al, idx1 + t * 8);
    }
}

// ---------------------------------------------------------------------------
extern "C" void kernel_launch(void* const* d_in, const int* in_sizes, int n_in,
                              void* d_out, int out_size)
{
    const float* x  = (const float*)d_in[0];
    const float* wq = (const float*)d_in[1];
    const float* wk = (const float*)d_in[2];
    const float* wv = (const float*)d_in[3];
    const float* wo = (const float*)d_in[4];
    float* out = (float*)d_out;

    const int gemm_smem  = 65536;
    const int flash_smem = 65536;
    cudaFuncSetAttribute(qkv_mma_kernel,
                         cudaFuncAttributeMaxDynamicSharedMemorySize, gemm_smem);
    cudaFuncSetAttribute(proj_mma_kernel,
                         cudaFuncAttributeMaxDynamicSharedMemorySize, gemm_smem);
    cudaFuncSetAttribute(flash_mma_kernel,
                         cudaFuncAttributeMaxDynamicSharedMemorySize, flash_smem);

    split_x_kernel<<<4096, 256>>>((const float4*)x);
    split_w_kernel<<<dim3(1024, 1, 4), 256>>>((const float4*)wq, (const float4*)wk,
                                              (const float4*)wv, (const float4*)wo);
    qkv_mma_kernel<<<dim3(8, 32, 3), 512, gemm_smem>>>();
    flash_mma_kernel<<<dim3(16, 64), 128, flash_smem>>>();
    proj_mma_kernel<<<dim3(8, 32), 512, gemm_smem>>>(out);
}

// round 7
// speedup vs baseline: 3.1063x; 1.1898x over previous
#include <cuda_runtime.h>
#include <cuda_bf16.h>
#include <cstdint>

#define HID   1024

// ------------------------- device scratch (no alloc allowed) ---------------
__device__ __nv_bfloat16 g_xh[4194304], g_xl[4194304];
__device__ __nv_bfloat16 g_wh[3145728], g_wl[3145728];   // wq|wk|wv
__device__ __nv_bfloat16 g_woh[1048576], g_wol[1048576];
__device__ __nv_bfloat16 g_qh[4194304], g_ql[4194304];   // flat (b,s,o), Q pre-scaled
__device__ __nv_bfloat16 g_kh[4194304], g_kl[4194304];
__device__ __nv_bfloat16 g_vh[4194304], g_vl[4194304];
__device__ __nv_bfloat16 g_ah[4194304], g_al[4194304];   // attention out, flat (b,s,o)

// ------------------------- helpers -----------------------------------------
__device__ __forceinline__ uint32_t smem_u32(const void* p) {
    uint32_t a;
    asm("{ .reg .u64 t; cvta.to.shared.u64 t, %1; cvt.u32.u64 %0, t; }"
        : "=r"(a) : "l"(p));
    return a;
}

#define SWZ128(bo) ((bo) ^ (((bo) >> 3) & 0x70))
#define SWZ64(bo)  ((bo) ^ (((bo) >> 3) & 0x30))

#define LDSM4(r, addr) \
    asm volatile("ldmatrix.sync.aligned.m8n8.x4.shared.b16 {%0,%1,%2,%3}, [%4];" \
                 : "=r"((r)[0]), "=r"((r)[1]), "=r"((r)[2]), "=r"((r)[3])       \
                 : "r"(addr))

#define LDSM4T(r, addr) \
    asm volatile("ldmatrix.sync.aligned.m8n8.x4.trans.shared.b16 {%0,%1,%2,%3}, [%4];" \
                 : "=r"((r)[0]), "=r"((r)[1]), "=r"((r)[2]), "=r"((r)[3])       \
                 : "r"(addr))

#define MMA16816(d, a, b0, b1) \
    asm volatile("mma.sync.aligned.m16n8k16.row.col.f32.bf16.bf16.f32 "         \
                 "{%0,%1,%2,%3}, {%4,%5,%6,%7}, {%8,%9}, {%0,%1,%2,%3};"        \
                 : "+f"((d)[0]), "+f"((d)[1]), "+f"((d)[2]), "+f"((d)[3])       \
                 : "r"((a)[0]), "r"((a)[1]), "r"((a)[2]), "r"((a)[3]),          \
                   "r"(b0), "r"(b1))

#define CP_ASYNC16(dst, src) \
    asm volatile("cp.async.cg.shared.global [%0], [%1], 16;" \
                 :: "r"(dst), "l"(src) : "memory")
#define CP_COMMIT()  asm volatile("cp.async.commit_group;" ::: "memory")
#define CP_WAIT0()   asm volatile("cp.async.wait_group 0;" ::: "memory")

// pack two floats into bf16x2 reg
__device__ __forceinline__ uint32_t packbf(float lo, float hi) {
    uint32_t r;
    asm("cvt.rn.bf16x2.f32 %0, %1, %2;" : "=r"(r) : "f"(hi), "f"(lo));
    return r;
}

__device__ __forceinline__ void split_store2(float x, float y,
                                             __nv_bfloat16* H, __nv_bfloat16* L,
                                             size_t idx) {
    __nv_bfloat16 hx = __float2bfloat16(x), hy = __float2bfloat16(y);
    __nv_bfloat162 h2, l2;
    h2.x = hx; h2.y = hy;
    l2.x = __float2bfloat16(x - __bfloat162float(hx));
    l2.y = __float2bfloat16(y - __bfloat162float(hy));
    *(__nv_bfloat162*)(H + idx) = h2;
    *(__nv_bfloat162*)(L + idx) = l2;
}

// ------------------------- fp32 -> bf16 hi/lo split ------------------------
__device__ __forceinline__ void split4_store(float4 v, __nv_bfloat16* hi,
                                             __nv_bfloat16* lo, int i) {
    __nv_bfloat16 h0 = __float2bfloat16(v.x), h1 = __float2bfloat16(v.y);
    __nv_bfloat16 h2 = __float2bfloat16(v.z), h3 = __float2bfloat16(v.w);
    __nv_bfloat162* H = (__nv_bfloat162*)hi;
    __nv_bfloat162* L = (__nv_bfloat162*)lo;
    __nv_bfloat162 p;
    p.x = h0; p.y = h1; H[2*i]   = p;
    p.x = h2; p.y = h3; H[2*i+1] = p;
    p.x = __float2bfloat16(v.x - __bfloat162float(h0));
    p.y = __float2bfloat16(v.y - __bfloat162float(h1));
    L[2*i]   = p;
    p.x = __float2bfloat16(v.z - __bfloat162float(h2));
    p.y = __float2bfloat16(v.w - __bfloat162float(h3));
    L[2*i+1] = p;
}

__global__ void __launch_bounds__(256) split_x_kernel(const float4* __restrict__ x) {
    int i = blockIdx.x * 256 + threadIdx.x;
    split4_store(x[i], g_xh, g_xl, i);
}
__global__ void __launch_bounds__(256) split_w_kernel(const float4* __restrict__ wq,
                                                      const float4* __restrict__ wk,
                                                      const float4* __restrict__ wv,
                                                      const float4* __restrict__ wo) {
    int z = blockIdx.z;
    const float4* s = (z == 0) ? wq : (z == 1) ? wk : (z == 2) ? wv : wo;
    __nv_bfloat16* hi = (z < 3) ? g_wh + (size_t)z * 1048576 : g_woh;
    __nv_bfloat16* lo = (z < 3) ? g_wl + (size_t)z * 1048576 : g_wol;
    int i = blockIdx.x * 256 + threadIdx.x;
    split4_store(s[i], hi, lo, i);
}

// ------------------------- HMMA GEMM (cp.async 2-stage pipeline) -----------
// C[4096 x 1024] = A * B^T via mma.sync m16n8k16 bf16, 3-term split.
// Block 128x128, BK=32, 512 threads, warp tile 32x32.
// smem: 2 stages x {Ah,Al,Bh,Bl} x 8KB (128 rows x 64B, SW64) = 64KB.
template <bool SPLIT_OUT>
__device__ __forceinline__ void mma_gemm_body(const __nv_bfloat16* __restrict__ Ah,
                                              const __nv_bfloat16* __restrict__ Al,
                                              const __nv_bfloat16* __restrict__ Bh,
                                              const __nv_bfloat16* __restrict__ Bl,
                                              float* __restrict__ C,
                                              __nv_bfloat16* __restrict__ Oh,
                                              __nv_bfloat16* __restrict__ Ol,
                                              float scale) {
    extern __shared__ char smem[];
    const uint32_t sb = smem_u32(smem);

    const int tid  = threadIdx.x;
    const int lane = tid & 31, wid = tid >> 5;
    const int wm = wid >> 2, wn = wid & 3;
    const int n0 = blockIdx.x * 128, m0 = blockIdx.y * 128;

    // cp.async source/dest (one 16B chunk per thread per tile per stage)
    const int lrow = tid >> 2, lch = tid & 3;
    const uint32_t sdst = SWZ64((uint32_t)(lrow * 64 + lch * 16));
    const __nv_bfloat16* pAh = Ah + (size_t)(m0 + lrow) * HID + lch * 8;
    const __nv_bfloat16* pAl = Al + (size_t)(m0 + lrow) * HID + lch * 8;
    const __nv_bfloat16* pBh = Bh + (size_t)(n0 + lrow) * HID + lch * 8;
    const __nv_bfloat16* pBl = Bl + (size_t)(n0 + lrow) * HID + lch * 8;

    // A fragment addressing (SW64: xor = ((row>>1)&3)<<4; same for row+16)
    const int ra = wm * 32 + (lane & 15);
    const uint32_t colA = (uint32_t)((lane >> 4) << 4);
    const uint32_t aX   = (uint32_t)(((ra >> 1) & 3) << 4);
    const uint32_t aR0  = (uint32_t)(ra * 64);
    const uint32_t aR1  = aR0 + 16 * 64;

    const int q = lane >> 3, r = lane & 7;
    const int rb = wn * 32 + ((q >> 1) << 3) + r;
    const uint32_t colB = (uint32_t)((q & 1) << 4);
    const uint32_t bX   = (uint32_t)(((rb >> 1) & 3) << 4);
    const uint32_t bR0  = (uint32_t)(rb * 64);
    const uint32_t bR1  = bR0 + 16 * 64;

    float acc[2][4][4];
#pragma unroll
    for (int mi = 0; mi < 2; ++mi)
#pragma unroll
        for (int nj = 0; nj < 4; ++nj)
#pragma unroll
            for (int e = 0; e < 4; ++e) acc[mi][nj][e] = 0.0f;

    // ---- issue stage 0 ----
    {
        const uint32_t b0 = sb + sdst;
        CP_ASYNC16(b0 +     0, pAh);
        CP_ASYNC16(b0 +  8192, pAl);
        CP_ASYNC16(b0 + 16384, pBh);
        CP_ASYNC16(b0 + 24576, pBl);
        CP_COMMIT();
    }

    for (int kt = 0; kt < 32; ++kt) {
        CP_WAIT0();
        __syncthreads();
        if (kt + 1 < 32) {
            const int k0 = (kt + 1) * 32;
            const uint32_t b0 = sb + (uint32_t)((kt + 1) & 1) * 32768 + sdst;
            CP_ASYNC16(b0 +     0, pAh + k0);
            CP_ASYNC16(b0 +  8192, pAl + k0);
            CP_ASYNC16(b0 + 16384, pBh + k0);
            CP_ASYNC16(b0 + 24576, pBl + k0);
            CP_COMMIT();
        }
        const uint32_t base = sb + (uint32_t)(kt & 1) * 32768;

#pragma unroll
        for (int ks = 0; ks < 2; ++ks) {
            const uint32_t cb = (uint32_t)(ks * 32);
            const uint32_t offA = (cb + colA) ^ aX;
            const uint32_t offB = (cb + colB) ^ bX;

            uint32_t ah[2][4], al[2][4], bh[2][4], bl[2][4];
            LDSM4(ah[0], base + aR0 + offA);
            LDSM4(ah[1], base + aR1 + offA);
            LDSM4(al[0], base + 8192 + aR0 + offA);
            LDSM4(al[1], base + 8192 + aR1 + offA);
            LDSM4(bh[0], base + 16384 + bR0 + offB);
            LDSM4(bh[1], base + 16384 + bR1 + offB);
            LDSM4(bl[0], base + 24576 + bR0 + offB);
            LDSM4(bl[1], base + 24576 + bR1 + offB);

#pragma unroll
            for (int mi = 0; mi < 2; ++mi)
#pragma unroll
                for (int nj = 0; nj < 4; ++nj) {
                    const int g = nj >> 1, h = (nj & 1) * 2;
                    MMA16816(acc[mi][nj], ah[mi], bh[g][h], bh[g][h + 1]);
                    MMA16816(acc[mi][nj], ah[mi], bl[g][h], bl[g][h + 1]);
                    MMA16816(acc[mi][nj], al[mi], bh[g][h], bh[g][h + 1]);
                }
        }
        __syncthreads();
    }

    const int crow = m0 + wm * 32 + (lane >> 2);
    const int ccol = n0 + wn * 32 + (lane & 3) * 2;
#pragma unroll
    for (int mi = 0; mi < 2; ++mi)
#pragma unroll
        for (int nj = 0; nj < 4; ++nj) {
            if (SPLIT_OUT) {
                // identity flat layout: raw view == flat storage
                size_t i0 = (size_t)(crow + mi * 16) * 1024 + (ccol + nj * 8);
                size_t i1 = i0 + 8 * 1024;
                split_store2(acc[mi][nj][0] * scale, acc[mi][nj][1] * scale, Oh, Ol, i0);
                split_store2(acc[mi][nj][2] * scale, acc[mi][nj][3] * scale, Oh, Ol, i1);
            } else {
                float* p0 = C + (size_t)(crow + mi * 16) * HID + ccol + nj * 8;
                float* p1 = p0 + 8 * HID;
                *(float2*)p0 = make_float2(acc[mi][nj][0], acc[mi][nj][1]);
                *(float2*)p1 = make_float2(acc[mi][nj][2], acc[mi][nj][3]);
            }
        }
}

__global__ void __launch_bounds__(512, 1) qkv_mma_kernel() {
    int z = blockIdx.z;
    const __nv_bfloat16* Bh = g_wh + (size_t)z * 1048576;
    const __nv_bfloat16* Bl = g_wl + (size_t)z * 1048576;
    __nv_bfloat16* Oh = (z == 0) ? g_qh : (z == 1) ? g_kh : g_vh;
    __nv_bfloat16* Ol = (z == 0) ? g_ql : (z == 1) ? g_kl : g_vl;
    float scale = (z == 0) ? 0.125f : 1.0f;   // fold softmax scale into Q
    mma_gemm_body<true>(g_xh, g_xl, Bh, Bl, nullptr, Oh, Ol, scale);
}
__global__ void __launch_bounds__(512, 1) proj_mma_kernel(float* __restrict__ out) {
    mma_gemm_body<false>(g_ah, g_al, g_woh, g_wol, out, nullptr, nullptr, 1.0f);
}

// ---------------------------------------------------------------------------
// Flash attention via HMMA, 3-term bf16 split on both QK^T and PV.
// Per-(b,h) head block = contiguous 65536-elt slice of the flat arrays (raw view).
// Block: 128 threads = 4 warps, Br=64 (16 rows/warp), Bc=64, 16 K-tiles.
// smem: 2 stages x {Kh,Kl,Vh,Vl} x 8KB = 64KB, cp.async double-buffered.
// ---------------------------------------------------------------------------
__device__ __forceinline__ void kv_issue(int tid, uint32_t sb, int stage,
                                         int kt, size_t base) {
    const size_t row0 = base + (size_t)kt * 64 * 64;
#pragma unroll
    for (int i = 0; i < 16; ++i) {
        int t = tid + i * 128;
        int tile = t >> 9;                 // 0:Kh 1:Kl 2:Vh 3:Vl
        int ww = t & 511, row = ww >> 3, c = ww & 7;
        const __nv_bfloat16* src =
            (tile == 0) ? g_kh : (tile == 1) ? g_kl : (tile == 2) ? g_vh : g_vl;
        src += row0 + (size_t)row * 64 + c * 8;
        uint32_t dst = sb + (uint32_t)stage * 32768 + (uint32_t)tile * 8192
                     + SWZ128((uint32_t)(row * 128 + c * 16));
        CP_ASYNC16(dst, src);
    }
}

__global__ void __launch_bounds__(128) flash_mma_kernel() {
    extern __shared__ char smem[];
    const uint32_t sb = smem_u32(smem);
    const int bh = blockIdx.y, qt = blockIdx.x;
    const int tid = threadIdx.x, lane = tid & 31, w = tid >> 5;
    const size_t base = (size_t)bh * 65536;

    // ---- stage Q (scaled, split) into stage0 area, load fragments ----
    {
        const __nv_bfloat16* Qhp = g_qh + base + (size_t)qt * 4096;
        const __nv_bfloat16* Qlp = g_ql + base + (size_t)qt * 4096;
#pragma unroll
        for (int i = 0; i < 8; ++i) {
            int t = tid + i * 128;
            int half = t >> 9, ww = t & 511, row = ww >> 3, c = ww & 7;
            const __nv_bfloat16* src = (half ? Qlp : Qhp) + row * 64 + c * 8;
            *(uint4*)(smem + half * 8192 + SWZ128((uint32_t)(row * 128 + c * 16)))
                = *(const uint4*)src;
        }
    }
    __syncthreads();

    uint32_t qh[4][4], ql[4][4];
    {
        const int ra = w * 16 + (lane & 15);
        const uint32_t colA = (uint32_t)((lane >> 4) << 4);
        const uint32_t aX   = (uint32_t)((ra & 7) << 4);
        const uint32_t qb   = sb + (uint32_t)ra * 128;
#pragma unroll
        for (int ks = 0; ks < 4; ++ks) {
            uint32_t off = ((uint32_t)(ks * 32) + colA) ^ aX;
            LDSM4(qh[ks], qb + off);
            LDSM4(ql[ks], qb + 8192 + off);
        }
    }
    __syncthreads();

    // K (B-operand, non-trans) addressing
    const int qq = lane >> 3, rr = lane & 7;
    const int rowK16 = ((qq >> 1) << 3) + rr;
    const uint32_t colBk = (uint32_t)((qq & 1) << 4);
    const uint32_t xK = (uint32_t)((rowK16 & 7) << 4);
    // V (B-operand via trans) addressing
    const int rowV = (lane & 7) + ((lane >> 3) & 1) * 8;
    const uint32_t colV16 = (uint32_t)(((lane >> 4) & 1) << 4);
    const uint32_t xV = (uint32_t)((rowV & 7) << 4);

    float o_[8][4];
#pragma unroll
    for (int t = 0; t < 8; ++t)
#pragma unroll
        for (int e = 0; e < 4; ++e) o_[t][e] = 0.0f;
    float m0v = -1e30f, m1v = -1e30f, l0 = 0.0f, l1 = 0.0f;

    kv_issue(tid, sb, 0, 0, base);
    CP_COMMIT();

    for (int kt = 0; kt < 16; ++kt) {
        CP_WAIT0();
        __syncthreads();
        if (kt + 1 < 16) {
            kv_issue(tid, sb, (kt + 1) & 1, kt + 1, base);
            CP_COMMIT();
        }
        const uint32_t kst = sb + (uint32_t)(kt & 1) * 32768;

        // ---- S = Qs K^T (3-term split) ----
        float s_[8][4];
#pragma unroll
        for (int t = 0; t < 8; ++t)
#pragma unroll
            for (int e = 0; e < 4; ++e) s_[t][e] = 0.0f;

#pragma unroll
        for (int sg = 0; sg < 4; ++sg) {
            const uint32_t rbase = kst + (uint32_t)((sg * 16 + rowK16) * 128);
#pragma unroll
            for (int ks = 0; ks < 4; ++ks) {
                const uint32_t off = ((uint32_t)(ks * 32) + colBk) ^ xK;
                uint32_t tkh[4], tkl[4];
                LDSM4(tkh, rbase + off);
                LDSM4(tkl, rbase + 8192 + off);
                MMA16816(s_[2*sg],   qh[ks], tkh[0], tkh[1]);
                MMA16816(s_[2*sg],   qh[ks], tkl[0], tkl[1]);
                MMA16816(s_[2*sg],   ql[ks], tkh[0], tkh[1]);
                MMA16816(s_[2*sg+1], qh[ks], tkh[2], tkh[3]);
                MMA16816(s_[2*sg+1], qh[ks], tkl[2], tkl[3]);
                MMA16816(s_[2*sg+1], ql[ks], tkh[2], tkh[3]);
            }
        }

        // ---- online softmax on fragments ----
        float mx0 = -1e30f, mx1 = -1e30f;
#pragma unroll
        for (int t = 0; t < 8; ++t) {
            mx0 = fmaxf(mx0, fmaxf(s_[t][0], s_[t][1]));
            mx1 = fmaxf(mx1, fmaxf(s_[t][2], s_[t][3]));
        }
        mx0 = fmaxf(mx0, __shfl_xor_sync(0xffffffffu, mx0, 1));
        mx0 = fmaxf(mx0, __shfl_xor_sync(0xffffffffu, mx0, 2));
        mx1 = fmaxf(mx1, __shfl_xor_sync(0xffffffffu, mx1, 1));
        mx1 = fmaxf(mx1, __shfl_xor_sync(0xffffffffu, mx1, 2));
        float mn0 = fmaxf(m0v, mx0), mn1 = fmaxf(m1v, mx1);
        float al0 = __expf(m0v - mn0), al1 = __expf(m1v - mn1);
        m0v = mn0; m1v = mn1;

        float rs0 = 0.0f, rs1 = 0.0f;
#pragma unroll
        for (int t = 0; t < 8; ++t) {
            s_[t][0] = __expf(s_[t][0] - mn0); rs0 += s_[t][0];
            s_[t][1] = __expf(s_[t][1] - mn0); rs0 += s_[t][1];
            s_[t][2] = __expf(s_[t][2] - mn1); rs1 += s_[t][2];
            s_[t][3] = __expf(s_[t][3] - mn1); rs1 += s_[t][3];
        }
        rs0 += __shfl_xor_sync(0xffffffffu, rs0, 1);
        rs0 += __shfl_xor_sync(0xffffffffu, rs0, 2);
        rs1 += __shfl_xor_sync(0xffffffffu, rs1, 1);
        rs1 += __shfl_xor_sync(0xffffffffu, rs1, 2);
        l0 = l0 * al0 + rs0;
        l1 = l1 * al1 + rs1;
#pragma unroll
        for (int t = 0; t < 8; ++t) {
            o_[t][0] *= al0; o_[t][1] *= al0;
            o_[t][2] *= al1; o_[t][3] *= al1;
        }

        // ---- O += P V (3-term split), P repacked in registers ----
        const uint32_t vst = kst + 16384;
#pragma unroll
        for (int j = 0; j < 4; ++j) {
            uint32_t pah[4], pal[4];
            {
                float c0 = s_[2*j][0],   c1 = s_[2*j][1];
                float c2 = s_[2*j][2],   c3 = s_[2*j][3];
                float d0 = s_[2*j+1][0], d1 = s_[2*j+1][1];
                float d2 = s_[2*j+1][2], d3 = s_[2*j+1][3];
                pah[0] = packbf(c0, c1);
                pah[1] = packbf(c2, c3);
                pah[2] = packbf(d0, d1);
                pah[3] = packbf(d2, d3);
                float r0f = c0 - __bfloat162float(__float2bfloat16(c0));
                float r1f = c1 - __bfloat162float(__float2bfloat16(c1));
                float r2f = c2 - __bfloat162float(__float2bfloat16(c2));
                float r3f = c3 - __bfloat162float(__float2bfloat16(c3));
                pal[0] = packbf(r0f, r1f);
                pal[1] = packbf(r2f, r3f);
                r0f = d0 - __bfloat162float(__float2bfloat16(d0));
                r1f = d1 - __bfloat162float(__float2bfloat16(d1));
                r2f = d2 - __bfloat162float(__float2bfloat16(d2));
                r3f = d3 - __bfloat162float(__float2bfloat16(d3));
                pal[2] = packbf(r0f, r1f);
                pal[3] = packbf(r2f, r3f);
            }
            const uint32_t rvb = vst + (uint32_t)((j * 16 + rowV) * 128);
#pragma unroll
            for (int dg = 0; dg < 4; ++dg) {
                const uint32_t off = ((uint32_t)(dg * 32) + colV16) ^ xV;
                uint32_t tvh[4], tvl[4];
                LDSM4T(tvh, rvb + off);
                LDSM4T(tvl, rvb + 8192 + off);
                MMA16816(o_[2*dg],   pah, tvh[0], tvh[1]);
                MMA16816(o_[2*dg],   pah, tvl[0], tvl[1]);
                MMA16816(o_[2*dg],   pal, tvh[0], tvh[1]);
                MMA16816(o_[2*dg+1], pah, tvh[2], tvh[3]);
                MMA16816(o_[2*dg+1], pah, tvl[2], tvl[3]);
                MMA16816(o_[2*dg+1], pal, tvh[2], tvh[3]);
            }
        }
    }

    // ---- epilogue: O/l -> bf16 hi/lo, identity flat layout (raw view) ----
    const float i0 = 1.0f / l0, i1 = 1.0f / l1;
    const int r0 = lane >> 2, cc = (lane & 3) * 2;
    const size_t idx0 = base + (size_t)(qt * 64 + w * 16 + r0) * 64 + cc;
    const size_t idx1 = idx0 + 8 * 64;
#pragma unroll
    for (int t = 0; t < 8; ++t) {
        split_store2(o_[t][0] * i0, o_[t][1] * i0, g_ah, g_al, idx0 + t * 8);
        split_store2(o_[t][2] * i1, o_[t][3] * i1, g_ah, g_al, idx1 + t * 8);
    }
}

// ---------------------------------------------------------------------------
extern "C" void kernel_launch(void* const* d_in, const int* in_sizes, int n_in,
                              void* d_out, int out_size)
{
    const float* x  = (const float*)d_in[0];
    const float* wq = (const float*)d_in[1];
    const float* wk = (const float*)d_in[2];
    const float* wv = (const float*)d_in[3];
    const float* wo = (const float*)d_in[4];
    float* out = (float*)d_out;

    const int gemm_smem  = 65536;
    const int flash_smem = 65536;
    cudaFuncSetAttribute(qkv_mma_kernel,
                         cudaFuncAttributeMaxDynamicSharedMemorySize, gemm_smem);
    cudaFuncSetAttribute(proj_mma_kernel,
                         cudaFuncAttributeMaxDynamicSharedMemorySize, gemm_smem);
    cudaFuncSetAttribute(flash_mma_kernel,
                         cudaFuncAttributeMaxDynamicSharedMemorySize, flash_smem);

    split_x_kernel<<<4096, 256>>>((const float4*)x);
    split_w_kernel<<<dim3(1024, 1, 4), 256>>>((const float4*)wq, (const float4*)wk,
                                              (const float4*)wv, (const float4*)wo);
    qkv_mma_kernel<<<dim3(8, 32, 3), 512, gemm_smem>>>();
    flash_mma_kernel<<<dim3(16, 64), 128, flash_smem>>>();
    proj_mma_kernel<<<dim3(8, 32), 512, gemm_smem>>>(out);
}